// round 9
// baseline (speedup 1.0000x reference)
#include <cuda_runtime.h>
#include <cuda_bf16.h>
#include <cuda_fp16.h>

#define N_NODES 50000
#define E_EDGES 800000
#define IN_DIM  128
#define FEAT    128   // HEADS*OUT_DIM
#define HEADS   4
#define OUT_D   32
#define NEG_SLOPE 0.2f
#define EPS_ 1e-16f

#define N_SBLKS ((N_NODES + 255) / 256)   // 196 scan blocks

// ---------------- scratch (static device globals; no allocation) -------------
__device__ uint2  g_hh4[N_NODES * 32];          // h as fp16 (half4 per lane), 12.8 MB
__device__ float4 g_asrc4[N_NODES];
__device__ float4 g_adst4[N_NODES];
__device__ float4 g_s4[N_NODES];                // segment sums of exp
__device__ float4 g_ex4[E_EDGES];               // per-edge exp(alpha)
__device__ uint2  g_ha4[E_EDGES];               // CSR-ordered alpha as half4 (8 B)
__device__ int    g_deg[N_NODES];
__device__ int    g_rowstart[N_NODES];
__device__ int    g_cursor[N_NODES];
__device__ int    g_esrc[E_EDGES];              // CSR: src node
__device__ int    g_total;                      // fused-scan base counter

__device__ __forceinline__ void red_add_v4(float* addr, float a, float b, float c, float d) {
    asm volatile("red.global.add.v4.f32 [%0], {%1,%2,%3,%4};"
                 :: "l"(addr), "f"(a), "f"(b), "f"(c), "f"(d) : "memory");
}

// ---------------- K1: h = x @ W^T  + fused node epilogue ---------------------
__global__ __launch_bounds__(256) void k_gemm(
    const float* __restrict__ x, const float* __restrict__ W,
    const float* __restrict__ att_src, const float* __restrict__ att_dst)
{
    __shared__ float W_sm[32][132];    // [kk][o]
    __shared__ float x_sm[64][32];     // [r][kk]

    const int tid  = threadIdx.x;
    const int lane = tid & 31;
    const int w    = tid >> 5;
    const int row0 = blockIdx.x * 64;

    if (blockIdx.x == 0 && tid == 0) g_total = 0;   // reset fused-scan counter

    float4 acc[8];
#pragma unroll
    for (int rr = 0; rr < 8; rr++) acc[rr] = make_float4(0.f, 0.f, 0.f, 0.f);

    for (int kc = 0; kc < IN_DIM; kc += 32) {
#pragma unroll
        for (int it = 0; it < 4; it++) {
            int f   = it * 256 + tid;
            int o   = f >> 3;
            int kq  = f & 7;
            float4 wv = *reinterpret_cast<const float4*>(&W[o * IN_DIM + kc + kq * 4]);
            W_sm[kq * 4 + 0][o] = wv.x;
            W_sm[kq * 4 + 1][o] = wv.y;
            W_sm[kq * 4 + 2][o] = wv.z;
            W_sm[kq * 4 + 3][o] = wv.w;
        }
#pragma unroll
        for (int it = 0; it < 2; it++) {
            int f  = it * 256 + tid;
            int r  = f >> 3;
            int kq = f & 7;
            int row = row0 + r;
            float4 xv = (row < N_NODES)
                ? *reinterpret_cast<const float4*>(&x[row * IN_DIM + kc + kq * 4])
                : make_float4(0.f, 0.f, 0.f, 0.f);
            *reinterpret_cast<float4*>(&x_sm[r][kq * 4]) = xv;
        }
        __syncthreads();

#pragma unroll
        for (int kq = 0; kq < 8; kq++) {
            float4 w0 = *reinterpret_cast<const float4*>(&W_sm[kq * 4 + 0][lane * 4]);
            float4 w1 = *reinterpret_cast<const float4*>(&W_sm[kq * 4 + 1][lane * 4]);
            float4 w2 = *reinterpret_cast<const float4*>(&W_sm[kq * 4 + 2][lane * 4]);
            float4 w3 = *reinterpret_cast<const float4*>(&W_sm[kq * 4 + 3][lane * 4]);
#pragma unroll
            for (int rr = 0; rr < 8; rr++) {
                float4 xv = *reinterpret_cast<const float4*>(&x_sm[w * 8 + rr][kq * 4]);
                acc[rr].x += xv.x * w0.x + xv.y * w1.x + xv.z * w2.x + xv.w * w3.x;
                acc[rr].y += xv.x * w0.y + xv.y * w1.y + xv.z * w2.y + xv.w * w3.y;
                acc[rr].z += xv.x * w0.z + xv.y * w1.z + xv.z * w2.z + xv.w * w3.z;
                acc[rr].w += xv.x * w0.w + xv.y * w1.w + xv.z * w2.w + xv.w * w3.w;
            }
        }
        __syncthreads();
    }

    // fused epilogue: a_src/a_dst dots, fp16 h store, s/deg init
    const int f0 = lane * 4;
    const int hsel = lane >> 3;
    float4 as4 = *reinterpret_cast<const float4*>(&att_src[f0]);
    float4 ad4 = *reinterpret_cast<const float4*>(&att_dst[f0]);

#pragma unroll
    for (int rr = 0; rr < 8; rr++) {
        int row = row0 + w * 8 + rr;
        bool valid = (row < N_NODES);

        float ps = acc[rr].x * as4.x + acc[rr].y * as4.y + acc[rr].z * as4.z + acc[rr].w * as4.w;
        float pd = acc[rr].x * ad4.x + acc[rr].y * ad4.y + acc[rr].z * ad4.z + acc[rr].w * ad4.w;
#pragma unroll
        for (int off = 4; off >= 1; off >>= 1) {
            ps += __shfl_xor_sync(0xffffffffu, ps, off);
            pd += __shfl_xor_sync(0xffffffffu, pd, off);
        }
        if (valid) {
            if ((lane & 7) == 0) {
                ((float*)g_asrc4)[row * 4 + hsel] = ps;
                ((float*)g_adst4)[row * 4 + hsel] = pd;
            }
            __half2 h01 = __floats2half2_rn(acc[rr].x, acc[rr].y);
            __half2 h23 = __floats2half2_rn(acc[rr].z, acc[rr].w);
            uint2 hv;
            hv.x = *reinterpret_cast<unsigned*>(&h01);
            hv.y = *reinterpret_cast<unsigned*>(&h23);
            g_hh4[row * 32 + lane] = hv;
            if (lane == 0) {
                g_s4[row] = make_float4(0.f, 0.f, 0.f, 0.f);
                g_deg[row] = 0;
            }
        }
    }
}

// ---------------- K2: exp(leakyrelu(alpha)) + segment sum + degree -----------
__global__ __launch_bounds__(256) void k_edge_pass(const int* __restrict__ ei)
{
    int e = blockIdx.x * blockDim.x + threadIdx.x;
    if (e >= E_EDGES) return;
    int src = ei[e];
    int dst = ei[E_EDGES + e];
    if ((unsigned)src >= N_NODES || (unsigned)dst >= N_NODES) return;
    float4 as = g_asrc4[src];
    float4 ad = g_adst4[dst];
    float v0 = as.x + ad.x; v0 = (v0 > 0.f) ? v0 : NEG_SLOPE * v0;
    float v1 = as.y + ad.y; v1 = (v1 > 0.f) ? v1 : NEG_SLOPE * v1;
    float v2 = as.z + ad.z; v2 = (v2 > 0.f) ? v2 : NEG_SLOPE * v2;
    float v3 = as.w + ad.w; v3 = (v3 > 0.f) ? v3 : NEG_SLOPE * v3;
    float e0 = __expf(v0), e1 = __expf(v1), e2 = __expf(v2), e3 = __expf(v3);
    g_ex4[e] = make_float4(e0, e1, e2, e3);
    red_add_v4(&g_s4[dst].x, e0, e1, e2, e3);
    atomicAdd(&g_deg[dst], 1);
}

// ---------------- fused scan: block-local scan + atomic block base -----------
// rowstart need not be the ordered prefix: any disjoint [base, base+deg) works.
__global__ __launch_bounds__(256) void k_scan_fused()
{
    __shared__ int sm[256];
    __shared__ int base_sm;
    int t = threadIdx.x;
    int i = blockIdx.x * 256 + t;
    int d = (i < N_NODES) ? g_deg[i] : 0;
    sm[t] = d;
    __syncthreads();
    for (int off = 1; off < 256; off <<= 1) {
        int v = (t >= off) ? sm[t - off] : 0;
        __syncthreads();
        sm[t] += v;
        __syncthreads();
    }
    if (t == 255) base_sm = atomicAdd(&g_total, sm[255]);
    __syncthreads();
    if (i < N_NODES) {
        int rs = base_sm + sm[t] - d;   // exclusive within block + block base
        g_rowstart[i] = rs;
        g_cursor[i]   = rs;
    }
}

// ---------------- K2c: CSR placement + final alpha (fp16) + pooled (fp32) ----
__global__ __launch_bounds__(256) void k_place(
    const int* __restrict__ ei, float* __restrict__ alpha_pooled)
{
    int e = blockIdx.x * blockDim.x + threadIdx.x;
    if (e >= E_EDGES) return;
    int src = ei[e];
    int dst = ei[E_EDGES + e];
    if ((unsigned)src >= N_NODES || (unsigned)dst >= N_NODES) return;
    float4 ex = g_ex4[e];
    float4 sv = g_s4[dst];
    float a0 = ex.x / (sv.x + EPS_);
    float a1 = ex.y / (sv.y + EPS_);
    float a2 = ex.z / (sv.z + EPS_);
    float a3 = ex.w / (sv.w + EPS_);
    alpha_pooled[e] = 0.25f * (a0 + a1 + a2 + a3);
    int pos = atomicAdd(&g_cursor[dst], 1);
    __half2 p01 = __floats2half2_rn(a0, a1);
    __half2 p23 = __floats2half2_rn(a2, a3);
    uint2 ha;
    ha.x = *reinterpret_cast<unsigned*>(&p01);
    ha.y = *reinterpret_cast<unsigned*>(&p23);
    g_ha4[pos]  = ha;
    g_esrc[pos] = src;
}

// ---------------- K3: per-dst aggregation (warp per node, fp16) --------------
__global__ __launch_bounds__(256) void k_agg(
    const float* __restrict__ bias, float* __restrict__ out)
{
    int warp = (blockIdx.x * blockDim.x + threadIdx.x) >> 5;
    int lane = threadIdx.x & 31;
    if (warp >= N_NODES) return;
    const int d     = warp;
    const int start = g_rowstart[d];
    const int deg   = g_deg[d];
    const int hsel  = lane >> 3;
    const int f0    = lane * 4;

    float4 acc = *reinterpret_cast<const float4*>(bias + f0);

    for (int j = 0; j < deg; j++) {
        int   src = g_esrc[start + j];
        uint2 ha  = g_ha4[start + j];
        float alpha = __half2float(reinterpret_cast<const __half*>(&ha)[hsel]);
        uint2 hv = g_hh4[src * 32 + lane];
        float2 f01 = __half22float2(*reinterpret_cast<__half2*>(&hv.x));
        float2 f23 = __half22float2(*reinterpret_cast<__half2*>(&hv.y));
        acc.x += f01.x * alpha;
        acc.y += f01.y * alpha;
        acc.z += f23.x * alpha;
        acc.w += f23.y * alpha;
    }
    *reinterpret_cast<float4*>(out + d * FEAT + f0) = acc;
}

// ---------------- launch -----------------------------------------------------
extern "C" void kernel_launch(void* const* d_in, const int* in_sizes, int n_in,
                              void* d_out, int out_size)
{
    const float* x      = (const float*)d_in[0];
    const int*   ei     = (const int*)d_in[1];
    const float* W      = (const float*)d_in[2];
    const float* attsrc = (const float*)d_in[3];
    const float* attdst = (const float*)d_in[4];
    const float* bias   = (const float*)d_in[5];

    float* out = (float*)d_out;
    float* alpha_pooled = (float*)d_out + ((size_t)out_size - E_EDGES);

    k_gemm<<<(N_NODES + 63) / 64, 256>>>(x, W, attsrc, attdst);
    k_edge_pass<<<(E_EDGES + 255) / 256, 256>>>(ei);
    k_scan_fused<<<N_SBLKS, 256>>>();
    k_place<<<(E_EDGES + 255) / 256, 256>>>(ei, alpha_pooled);
    k_agg<<<(N_NODES * 32 + 255) / 256, 256>>>(bias, out);
}